// round 5
// baseline (speedup 1.0000x reference)
#include <cuda_runtime.h>
#include <cstdint>

// GraphAttention fused, mma.sync tf32, 512-thread version (16 warps, 64x32 warp tile).
// Phase1: h = x @ Ww^T + Wb (128x256x512). Phase2: softmax in SMEM.
// Phase3: out = alpha @ h (128x256x128). fp32 accumulate, tf32 RN inputs.

#define B_ 256
#define C_ 128
#define T_ 512
#define H_ 256
#define KC 32
#define CHUNKS 16
#define THREADS 512

// SMEM float offsets
#define XSTR 36
#define WSTR 36
#define HSTR 264
#define ASTR 132
#define STAGE_F 13824            // per-stage floats: x 128*36 + W 256*36
#define WOFF 4608                // W tile offset within a stage
#define ALPHA_F 33792            // h region: 128*264 floats (aliases stages)
#define MISC_F  (ALPHA_F + 16896)
// misc sub-offsets (floats from misc base)
#define M_WB   0
#define M_ASRC 256
#define M_ADST 512
#define M_FP   768
#define M_GP   1280
#define M_FV   1792
#define M_GV   1920
#define M_SP   2048
#define M_SINV 2560
#define M_AB   2688
#define SM_FLOATS (MISC_F + 2816)
#define SMEM_BYTES (SM_FLOATS * 4)

__device__ __forceinline__ uint32_t smem_u32(const void* p) {
    uint32_t a;
    asm("{ .reg .u64 t; cvta.to.shared.u64 t, %1; cvt.u32.u64 %0, t; }" : "=r"(a) : "l"(p));
    return a;
}

#define CP_ASYNC16(dst_u32, src_ptr) \
    asm volatile("cp.async.cg.shared.global [%0], [%1], 16;" :: "r"(dst_u32), "l"(src_ptr) : "memory")
#define CP_COMMIT() asm volatile("cp.async.commit_group;" ::: "memory")
#define CP_WAIT(n)  asm volatile("cp.async.wait_group %0;" :: "n"(n) : "memory")

__device__ __forceinline__ uint32_t f2tf(float x) {
    uint32_t r;
    asm("cvt.rna.tf32.f32 %0, %1;" : "=r"(r) : "f"(x));
    return r;
}

// tf32 round, returned as float (b32 cvt destination, then bit-reinterpret)
__device__ __forceinline__ float tf32r(float x) {
    return __uint_as_float(f2tf(x));
}

__device__ __forceinline__ void mma8(float* c, const uint32_t* a, const uint32_t* b) {
    asm volatile(
        "mma.sync.aligned.m16n8k8.row.col.f32.tf32.tf32.f32 "
        "{%0,%1,%2,%3}, {%4,%5,%6,%7}, {%8,%9}, {%0,%1,%2,%3};"
        : "+f"(c[0]), "+f"(c[1]), "+f"(c[2]), "+f"(c[3])
        : "r"(a[0]), "r"(a[1]), "r"(a[2]), "r"(a[3]), "r"(b[0]), "r"(b[1]));
}

__global__ __launch_bounds__(THREADS, 1)
void gat_mma_kernel(const float* __restrict__ x,
                    const float* __restrict__ Ww,
                    const float* __restrict__ Wb,
                    const float* __restrict__ aw,
                    const float* __restrict__ ab,
                    float* __restrict__ out)
{
    extern __shared__ float sm[];
    float* hsm   = sm;                 // stride HSTR, 128 rows (aliases stages)
    float* alpha = sm + ALPHA_F;       // stride ASTR, 128 rows
    float* misc  = sm + MISC_F;

    const int tid  = threadIdx.x;
    const int lane = tid & 31;
    const int warp = tid >> 5;
    const int wr   = warp >> 3;        // 0..1: row block (64 rows)
    const int wc   = warp & 7;         // 0..7: col block (32 cols)
    const int b    = blockIdx.x;

    const float* xb = x + (size_t)b * C_ * T_;

    // param preload
    if (tid < 256) {
        misc[M_WB + tid]   = Wb[tid];
        misc[M_ASRC + tid] = aw[tid];
        misc[M_ADST + tid] = aw[H_ + tid];
    }
    if (tid == 0) misc[M_AB] = ab[0];

    const uint32_t stage_u32 = smem_u32(sm);

    // staging: chunk c -> stage s (row-major, k-contiguous, stride 36)
    auto issue_chunk = [&](int c, int s) {
        uint32_t base = stage_u32 + (uint32_t)s * (STAGE_F * 4);
        const float* xsrc = xb + c * KC;
        #pragma unroll
        for (int i = 0; i < 2; i++) {
            int idx = tid + i * THREADS;           // < 1024
            int row = idx >> 3, slot = idx & 7;
            CP_ASYNC16(base + (uint32_t)(row * XSTR + slot * 4) * 4,
                       xsrc + row * T_ + slot * 4);
        }
        const float* wsrc = Ww + c * KC;
        #pragma unroll
        for (int i = 0; i < 4; i++) {
            int idx = tid + i * THREADS;           // < 2048
            int row = idx >> 3, slot = idx & 7;
            CP_ASYNC16(base + (uint32_t)(WOFF + row * WSTR + slot * 4) * 4,
                       wsrc + row * T_ + slot * 4);
        }
        CP_COMMIT();
    };

    issue_chunk(0, 0);
    issue_chunk(1, 1);

    float acc[4][4][4];
    #pragma unroll
    for (int mb = 0; mb < 4; mb++)
        #pragma unroll
        for (int nb = 0; nb < 4; nb++)
            #pragma unroll
            for (int q = 0; q < 4; q++) acc[mb][nb][q] = 0.f;

    const int lq = lane >> 2;   // 0..7
    const int lk = lane & 3;    // 0..3

    // ---- Phase 1: h = x @ Ww^T ----
    for (int c = 0; c < CHUNKS; c++) {
        if (c < CHUNKS - 2) CP_WAIT(1); else CP_WAIT(0);
        __syncthreads();

        const float* xs = sm + (c & 1) * STAGE_F;
        const float* ws = xs + WOFF;

        #pragma unroll
        for (int kq = 0; kq < 4; kq++) {
            const int k0 = kq * 8;
            uint32_t afr[4][4];
            #pragma unroll
            for (int mb = 0; mb < 4; mb++) {
                int r = wr * 64 + mb * 16 + lq;
                afr[mb][0] = f2tf(xs[r * XSTR + k0 + lk]);
                afr[mb][1] = f2tf(xs[(r + 8) * XSTR + k0 + lk]);
                afr[mb][2] = f2tf(xs[r * XSTR + k0 + 4 + lk]);
                afr[mb][3] = f2tf(xs[(r + 8) * XSTR + k0 + 4 + lk]);
            }
            uint32_t bfr[4][2];
            #pragma unroll
            for (int nb = 0; nb < 4; nb++) {
                int j = wc * 32 + nb * 8 + lq;
                bfr[nb][0] = f2tf(ws[j * WSTR + k0 + lk]);
                bfr[nb][1] = f2tf(ws[j * WSTR + k0 + 4 + lk]);
            }
            #pragma unroll
            for (int mb = 0; mb < 4; mb++)
                #pragma unroll
                for (int nb = 0; nb < 4; nb++)
                    mma8(acc[mb][nb], afr[mb], bfr[nb]);
        }
        __syncthreads();
        if (c + 2 < CHUNKS) issue_chunk(c + 2, c & 1);
    }

    // ---- Epilogue 1: h = acc + bias (tf32-rounded) -> SMEM (stride 264) ----
    #pragma unroll
    for (int mb = 0; mb < 4; mb++) {
        int r  = wr * 64 + mb * 16 + lq;
        int r2 = r + 8;
        #pragma unroll
        for (int nb = 0; nb < 4; nb++) {
            int j0 = wc * 32 + nb * 8 + 2 * lk;
            float b0 = misc[M_WB + j0], b1 = misc[M_WB + j0 + 1];
            float2 v0 = make_float2(tf32r(acc[mb][nb][0] + b0), tf32r(acc[mb][nb][1] + b1));
            float2 v1 = make_float2(tf32r(acc[mb][nb][2] + b0), tf32r(acc[mb][nb][3] + b1));
            *(float2*)&hsm[r  * HSTR + j0] = v0;
            *(float2*)&hsm[r2 * HSTR + j0] = v1;
        }
    }
    __syncthreads();

    // ---- f, g (4-way column partials) ----
    {
        const int row = tid & 127, part = tid >> 7;     // part: 0..3
        float f_ = 0.f, g_ = 0.f;
        const int j0 = part * 64;
        #pragma unroll 4
        for (int jj = 0; jj < 64; jj += 4) {
            int j = j0 + jj;
            float4 hv  = *(const float4*)&hsm[row * HSTR + j];
            float4 as_ = *(const float4*)&misc[M_ASRC + j];
            float4 ad_ = *(const float4*)&misc[M_ADST + j];
            f_ += hv.x * as_.x + hv.y * as_.y + hv.z * as_.z + hv.w * as_.w;
            g_ += hv.x * ad_.x + hv.y * ad_.y + hv.z * ad_.z + hv.w * ad_.w;
        }
        misc[M_FP + part * 128 + row] = f_;
        misc[M_GP + part * 128 + row] = g_;
    }
    __syncthreads();
    if (tid < 128) {
        misc[M_FV + tid] = (misc[M_FP + tid] + misc[M_FP + 128 + tid]) +
                           (misc[M_FP + 256 + tid] + misc[M_FP + 384 + tid]);
        misc[M_GV + tid] = (misc[M_GP + tid] + misc[M_GP + 128 + tid]) +
                           (misc[M_GP + 256 + tid] + misc[M_GP + 384 + tid]);
    }
    __syncthreads();

    // ---- Phase 2: softmax over i (4-way i partials per column j) ----
    {
        const int j = tid & 127, part = tid >> 7;
        const float gj = misc[M_GV + j] + misc[M_AB];
        float s = 0.f;
        const int i0 = part * 32;
        #pragma unroll 4
        for (int i = i0; i < i0 + 32; i++) {
            float z = misc[M_FV + i] + gj;
            z = (z > 0.f) ? z : 0.2f * z;
            float ex = __expf(z);
            alpha[i * ASTR + j] = ex;
            s += ex;
        }
        misc[M_SP + part * 128 + j] = s;
        __syncthreads();
        if (tid < 128)
            misc[M_SINV + tid] = 1.0f /
                ((misc[M_SP + tid] + misc[M_SP + 128 + tid]) +
                 (misc[M_SP + 256 + tid] + misc[M_SP + 384 + tid]));
        __syncthreads();
        const float iv = misc[M_SINV + j];
        #pragma unroll 4
        for (int i = i0; i < i0 + 32; i++)
            alpha[i * ASTR + j] = tf32r(alpha[i * ASTR + j] * iv);
    }
    __syncthreads();

    // ---- Phase 3: out = alpha @ h (operands pre-rounded: raw bit fragments) ----
    #pragma unroll
    for (int mb = 0; mb < 4; mb++)
        #pragma unroll
        for (int nb = 0; nb < 4; nb++)
            #pragma unroll
            for (int q = 0; q < 4; q++) acc[mb][nb][q] = 0.f;

    #pragma unroll 4
    for (int kq = 0; kq < 16; kq++) {
        const int k0 = kq * 8;
        uint32_t afr[4][4];
        #pragma unroll
        for (int mb = 0; mb < 4; mb++) {
            int r = wr * 64 + mb * 16 + lq;
            afr[mb][0] = __float_as_uint(alpha[r * ASTR + k0 + lk]);
            afr[mb][1] = __float_as_uint(alpha[(r + 8) * ASTR + k0 + lk]);
            afr[mb][2] = __float_as_uint(alpha[r * ASTR + k0 + 4 + lk]);
            afr[mb][3] = __float_as_uint(alpha[(r + 8) * ASTR + k0 + 4 + lk]);
        }
        uint32_t bfr[4][2];
        #pragma unroll
        for (int nb = 0; nb < 4; nb++) {
            int j = wc * 32 + nb * 8 + lq;
            bfr[nb][0] = __float_as_uint(hsm[(k0 + lk) * HSTR + j]);
            bfr[nb][1] = __float_as_uint(hsm[(k0 + 4 + lk) * HSTR + j]);
        }
        #pragma unroll
        for (int mb = 0; mb < 4; mb++)
            #pragma unroll
            for (int nb = 0; nb < 4; nb++)
                mma8(acc[mb][nb], afr[mb], bfr[nb]);
    }

    // ---- Epilogue 2: store out ----
    {
        float* ob = out + (size_t)b * C_ * H_;
        #pragma unroll
        for (int mb = 0; mb < 4; mb++) {
            int r  = wr * 64 + mb * 16 + lq;
            int r2 = r + 8;
            #pragma unroll
            for (int nb = 0; nb < 4; nb++) {
                int j0 = wc * 32 + nb * 8 + 2 * lk;
                *(float2*)&ob[r  * H_ + j0] = make_float2(acc[mb][nb][0], acc[mb][nb][1]);
                *(float2*)&ob[r2 * H_ + j0] = make_float2(acc[mb][nb][2], acc[mb][nb][3]);
            }
        }
    }
}

extern "C" void kernel_launch(void* const* d_in, const int* in_sizes, int n_in,
                              void* d_out, int out_size)
{
    const float* x  = (const float*)d_in[0];
    const float* Ww = (const float*)d_in[1];
    const float* Wb = (const float*)d_in[2];
    const float* aw = (const float*)d_in[3];
    const float* ab = (const float*)d_in[4];
    float* out = (float*)d_out;

    cudaFuncSetAttribute(gat_mma_kernel,
                         cudaFuncAttributeMaxDynamicSharedMemorySize, SMEM_BYTES);

    gat_mma_kernel<<<B_, THREADS, SMEM_BYTES>>>(x, Ww, Wb, aw, ab, out);
}

// round 6
// speedup vs baseline: 1.4825x; 1.4825x over previous
#include <cuda_runtime.h>
#include <cuda_fp16.h>
#include <cstdint>

// GraphAttention fused, mma.sync fp16 m16n8k16 (half the mma instructions of tf32).
// 512 threads, 16 warps (2x8 grid, 64x32 warp tiles). fp32 accumulate.
// Phase1: h = x @ Ww^T + Wb (staged to fp16 SMEM, LDG->cvt->STS double buffer).
// Phase2: softmax in SMEM (f,g from f32 accumulators). Phase3: out = alpha @ h.

#define B_ 256
#define C_ 128
#define T_ 512
#define H_ 256
#define KC 32
#define CHUNKS 16
#define THREADS 512

#define XROW 40              // fp16 elements per stage row (32 used + pad; 20 words, 20*lq mod 32 spreads)
#define HROW 136             // fp16 elements per hT/alphaH row (68 words; 4*lq spread)

// byte offsets in dynamic smem
#define ST0   0              // stage 0: x 128*40*2 = 10240, W 256*40*2 = 20480
#define ST1   30720
#define WOFF2 10240
#define HT    61440          // hT: 256 x HROW fp16 (69632 B)
#define AH    131072         // alphaH: 128 x HROW fp16 (34816 B)
#define MISCB 165888
// misc f32 indices
#define M_WB   0
#define M_ASRC 256
#define M_ADST 512
#define M_FP   768           // 8 x 128
#define M_GP   1792          // 8 x 128
#define M_FV   2816
#define M_GV   2944
#define M_SP   3072          // 4 x 128
#define M_SINV 3584
#define M_AB   3712
#define SMEM_BYTES (MISCB + 3720 * 4)

__device__ __forceinline__ void mma16(float* c, const uint32_t* a, const uint32_t* b) {
    asm volatile(
        "mma.sync.aligned.m16n8k16.row.col.f32.f16.f16.f32 "
        "{%0,%1,%2,%3}, {%4,%5,%6,%7}, {%8,%9}, {%0,%1,%2,%3};"
        : "+f"(c[0]), "+f"(c[1]), "+f"(c[2]), "+f"(c[3])
        : "r"(a[0]), "r"(a[1]), "r"(a[2]), "r"(a[3]), "r"(b[0]), "r"(b[1]));
}

__device__ __forceinline__ uint32_t pack2(float lo, float hi) {
    __half2 h = __floats2half2_rn(lo, hi);
    return *(const uint32_t*)&h;
}

__global__ __launch_bounds__(THREADS, 1)
void gat_fp16_kernel(const float* __restrict__ x,
                     const float* __restrict__ Ww,
                     const float* __restrict__ Wb,
                     const float* __restrict__ aw,
                     const float* __restrict__ ab,
                     float* __restrict__ out)
{
    extern __shared__ char smc[];
    float* misc = (float*)(smc + MISCB);

    const int tid  = threadIdx.x;
    const int lane = tid & 31;
    const int warp = tid >> 5;
    const int wr   = warp >> 3;      // 0..1: 64-row block
    const int wc   = warp & 7;       // 0..7: 32-col block
    const int lq   = lane >> 2;      // 0..7
    const int lk   = lane & 3;       // 0..3
    const int b    = blockIdx.x;

    const float* xb = x + (size_t)b * C_ * T_;

    // param preload
    if (tid < 256) {
        misc[M_WB + tid]   = Wb[tid];
        misc[M_ASRC + tid] = aw[tid];
        misc[M_ADST + tid] = aw[H_ + tid];
    }
    if (tid == 0) misc[M_AB] = ab[0];

    // staging thread mapping: x: 2 float4 (rows tid>>3, +64); W: 4 float4 (rows tid>>3 + 64i)
    const int srow = tid >> 3;       // 0..63
    const int sslot = tid & 7;       // 0..7 (k/4)

    float4 px[2], pw[4];

    auto ldg_chunk = [&](int c) {
        const float* xsrc = xb + c * KC;
        const float* wsrc = Ww + c * KC;
        #pragma unroll
        for (int i = 0; i < 2; i++)
            px[i] = *(const float4*)(xsrc + (srow + 64 * i) * T_ + sslot * 4);
        #pragma unroll
        for (int i = 0; i < 4; i++)
            pw[i] = *(const float4*)(wsrc + (srow + 64 * i) * T_ + sslot * 4);
    };

    auto sts_chunk = [&](int stage_byte) {
        __half* xs = (__half*)(smc + stage_byte);
        __half* ws = (__half*)(smc + stage_byte + WOFF2);
        #pragma unroll
        for (int i = 0; i < 2; i++) {
            uint2 u;
            u.x = pack2(px[i].x, px[i].y);
            u.y = pack2(px[i].z, px[i].w);
            *(uint2*)(xs + (srow + 64 * i) * XROW + sslot * 4) = u;
        }
        #pragma unroll
        for (int i = 0; i < 4; i++) {
            uint2 u;
            u.x = pack2(pw[i].x, pw[i].y);
            u.y = pack2(pw[i].z, pw[i].w);
            *(uint2*)(ws + (srow + 64 * i) * XROW + sslot * 4) = u;
        }
    };

    float acc[4][4][4];
    #pragma unroll
    for (int mb = 0; mb < 4; mb++)
        #pragma unroll
        for (int nb = 0; nb < 4; nb++)
            #pragma unroll
            for (int q = 0; q < 4; q++) acc[mb][nb][q] = 0.f;

    ldg_chunk(0);
    sts_chunk(ST0);
    ldg_chunk(1);

    // ---- Phase 1: h = x @ Ww^T ----
    for (int c = 0; c < CHUNKS; c++) {
        __syncthreads();
        if (c + 1 < CHUNKS) {
            sts_chunk((c + 1) & 1 ? ST1 : ST0);
            if (c + 2 < CHUNKS) ldg_chunk(c + 2);
        }
        const __half* xs = (const __half*)(smc + ((c & 1) ? ST1 : ST0));
        const __half* ws = (const __half*)(smc + ((c & 1) ? ST1 : ST0) + WOFF2);

        #pragma unroll
        for (int kq = 0; kq < 2; kq++) {
            const int k0 = kq * 16;
            uint32_t afr[4][4];
            #pragma unroll
            for (int mb = 0; mb < 4; mb++) {
                int r = wr * 64 + mb * 16 + lq;
                afr[mb][0] = *(const uint32_t*)(xs + r * XROW + k0 + 2 * lk);
                afr[mb][1] = *(const uint32_t*)(xs + (r + 8) * XROW + k0 + 2 * lk);
                afr[mb][2] = *(const uint32_t*)(xs + r * XROW + k0 + 8 + 2 * lk);
                afr[mb][3] = *(const uint32_t*)(xs + (r + 8) * XROW + k0 + 8 + 2 * lk);
            }
            uint32_t bfr[4][2];
            #pragma unroll
            for (int nb = 0; nb < 4; nb++) {
                int j = wc * 32 + nb * 8 + lq;
                bfr[nb][0] = *(const uint32_t*)(ws + j * XROW + k0 + 2 * lk);
                bfr[nb][1] = *(const uint32_t*)(ws + j * XROW + k0 + 8 + 2 * lk);
            }
            #pragma unroll
            for (int mb = 0; mb < 4; mb++)
                #pragma unroll
                for (int nb = 0; nb < 4; nb++)
                    mma16(acc[mb][nb], afr[mb], bfr[nb]);
        }
    }
    __syncthreads();

    // ---- Epilogue 1: bias add; f,g partials from f32 acc; hT (fp16) ----
    {
        __half* ht = (__half*)(smc + HT);
        #pragma unroll
        for (int mb = 0; mb < 4; mb++) {
            #pragma unroll
            for (int half = 0; half < 2; half++) {
                int r = wr * 64 + mb * 16 + lq + half * 8;
                float f_ = 0.f, g_ = 0.f;
                #pragma unroll
                for (int nb = 0; nb < 4; nb++) {
                    #pragma unroll
                    for (int q = 0; q < 2; q++) {
                        int col = wc * 32 + nb * 8 + 2 * lk + q;
                        float hv = acc[mb][nb][half * 2 + q] + misc[M_WB + col];
                        f_ += hv * misc[M_ASRC + col];
                        g_ += hv * misc[M_ADST + col];
                        ht[col * HROW + r] = __float2half_rn(hv);
                    }
                }
                // reduce over lk (lanes differing in bits 0..1)
                f_ += __shfl_xor_sync(0xFFFFFFFF, f_, 1);
                f_ += __shfl_xor_sync(0xFFFFFFFF, f_, 2);
                g_ += __shfl_xor_sync(0xFFFFFFFF, g_, 1);
                g_ += __shfl_xor_sync(0xFFFFFFFF, g_, 2);
                if (lk == 0) {
                    misc[M_FP + wc * 128 + r] = f_;
                    misc[M_GP + wc * 128 + r] = g_;
                }
            }
        }
    }
    __syncthreads();
    if (tid < 128) {
        float s = 0.f;
        #pragma unroll
        for (int p = 0; p < 8; p++) s += misc[M_FP + p * 128 + tid];
        misc[M_FV + tid] = s;
    } else if (tid < 256) {
        int r = tid - 128;
        float s = 0.f;
        #pragma unroll
        for (int p = 0; p < 8; p++) s += misc[M_GP + p * 128 + r];
        misc[M_GV + r] = s;
    }
    __syncthreads();

    // ---- Phase 2: softmax over i; alpha -> fp16 (row-major, k=j contiguous) ----
    {
        __half* ah = (__half*)(smc + AH);
        const int j = tid & 127, part = tid >> 7;   // 4 parts x 32 i's
        const float gj = misc[M_GV + j] + misc[M_AB];
        float s = 0.f;
        const int i0 = part * 32;
        #pragma unroll 4
        for (int i = i0; i < i0 + 32; i++) {
            float z = misc[M_FV + i] + gj;
            z = (z > 0.f) ? z : 0.2f * z;
            float ex = __expf(z);
            ah[i * HROW + j] = __float2half_rn(ex);
            s += ex;
        }
        misc[M_SP + part * 128 + j] = s;
        __syncthreads();
        if (tid < 128)
            misc[M_SINV + tid] = 1.0f /
                ((misc[M_SP + tid] + misc[M_SP + 128 + tid]) +
                 (misc[M_SP + 256 + tid] + misc[M_SP + 384 + tid]));
        __syncthreads();
        const float iv = misc[M_SINV + j];
        #pragma unroll 4
        for (int i = i0; i < i0 + 32; i++) {
            __half* p = ah + i * HROW + j;
            *p = __float2half_rn(__half2float(*p) * iv);
        }
    }
    __syncthreads();

    // ---- Phase 3: out = alpha @ h (fp16 operands, K=128) ----
    #pragma unroll
    for (int mb = 0; mb < 4; mb++)
        #pragma unroll
        for (int nb = 0; nb < 4; nb++)
            #pragma unroll
            for (int q = 0; q < 4; q++) acc[mb][nb][q] = 0.f;

    {
        const __half* ah = (const __half*)(smc + AH);
        const __half* ht = (const __half*)(smc + HT);
        #pragma unroll 2
        for (int kq = 0; kq < 8; kq++) {
            const int k0 = kq * 16;
            uint32_t afr[4][4];
            #pragma unroll
            for (int mb = 0; mb < 4; mb++) {
                int r = wr * 64 + mb * 16 + lq;
                afr[mb][0] = *(const uint32_t*)(ah + r * HROW + k0 + 2 * lk);
                afr[mb][1] = *(const uint32_t*)(ah + (r + 8) * HROW + k0 + 2 * lk);
                afr[mb][2] = *(const uint32_t*)(ah + r * HROW + k0 + 8 + 2 * lk);
                afr[mb][3] = *(const uint32_t*)(ah + (r + 8) * HROW + k0 + 8 + 2 * lk);
            }
            uint32_t bfr[4][2];
            #pragma unroll
            for (int nb = 0; nb < 4; nb++) {
                int j = wc * 32 + nb * 8 + lq;
                bfr[nb][0] = *(const uint32_t*)(ht + j * HROW + k0 + 2 * lk);
                bfr[nb][1] = *(const uint32_t*)(ht + j * HROW + k0 + 8 + 2 * lk);
            }
            #pragma unroll
            for (int mb = 0; mb < 4; mb++)
                #pragma unroll
                for (int nb = 0; nb < 4; nb++)
                    mma16(acc[mb][nb], afr[mb], bfr[nb]);
        }
    }

    // ---- Epilogue 2: store out ----
    {
        float* ob = out + (size_t)b * C_ * H_;
        #pragma unroll
        for (int mb = 0; mb < 4; mb++) {
            int r  = wr * 64 + mb * 16 + lq;
            int r2 = r + 8;
            #pragma unroll
            for (int nb = 0; nb < 4; nb++) {
                int j0 = wc * 32 + nb * 8 + 2 * lk;
                *(float2*)&ob[r  * H_ + j0] = make_float2(acc[mb][nb][0], acc[mb][nb][1]);
                *(float2*)&ob[r2 * H_ + j0] = make_float2(acc[mb][nb][2], acc[mb][nb][3]);
            }
        }
    }
}

extern "C" void kernel_launch(void* const* d_in, const int* in_sizes, int n_in,
                              void* d_out, int out_size)
{
    const float* x  = (const float*)d_in[0];
    const float* Ww = (const float*)d_in[1];
    const float* Wb = (const float*)d_in[2];
    const float* aw = (const float*)d_in[3];
    const float* ab = (const float*)d_in[4];
    float* out = (float*)d_out;

    cudaFuncSetAttribute(gat_fp16_kernel,
                         cudaFuncAttributeMaxDynamicSharedMemorySize, SMEM_BYTES);

    gat_fp16_kernel<<<B_, THREADS, SMEM_BYTES>>>(x, Ww, Wb, aw, ab, out);
}

// round 8
// speedup vs baseline: 1.5683x; 1.0579x over previous
#include <cuda_runtime.h>
#include <cuda_fp16.h>
#include <cstdint>

// GraphAttention fused, mma.sync fp16 m16n8k16 + ldmatrix fragment loads.
// 512 threads, 16 warps (2x8 grid, 64x32 warp tiles). fp32 accumulate.
// Phase1: h = x @ Ww^T + Wb (fp16 staged, LDG->cvt->STS double buffer, ldmatrix frags).
// Phase2: softmax in SMEM (f,g from f32 accumulators).
// Phase3: out = alpha @ h (A: ldmatrix, B: ldmatrix.trans on row-major h, stride 264).

#define B_ 256
#define C_ 128
#define T_ 512
#define H_ 256
#define KC 32
#define CHUNKS 16
#define THREADS 512

#define XROW 40              // stage row stride (halves); 80 B step, ldmatrix conflict-free
#define HTROW 264            // h row-major stride (halves): 256 cols + pad; 528 B = 4-bank step
#define AROW 136             // alpha row stride (halves): 128 cols + pad; 272 B = 4-bank step

// byte offsets in dynamic smem
#define ST0   0              // stage 0: x 128*40*2 = 10240 B, W 256*40*2 = 20480 B
#define ST1   30720
#define WOFF2 10240
#define HT    61440          // h row-major: 128 x HTROW fp16 = 67584 B
#define AH    129024         // alpha: 128 x AROW fp16 = 34816 B
#define MISCB 163840
// misc f32 indices
#define M_WB   0
#define M_ASRC 256
#define M_ADST 512
#define M_FP   768           // 8 x 128
#define M_GP   1792          // 8 x 128
#define M_FV   2816
#define M_GV   2944
#define M_SP   3072          // 4 x 128
#define M_SINV 3584
#define M_AB   3712
#define SMEM_BYTES (MISCB + 3720 * 4)

__device__ __forceinline__ uint32_t smem_u32(const void* p) {
    uint32_t a;
    asm("{ .reg .u64 t; cvta.to.shared.u64 t, %1; cvt.u32.u64 %0, t; }" : "=r"(a) : "l"(p));
    return a;
}

__device__ __forceinline__ void mma16(float* c, const uint32_t* a, const uint32_t* b) {
    asm volatile(
        "mma.sync.aligned.m16n8k16.row.col.f32.f16.f16.f32 "
        "{%0,%1,%2,%3}, {%4,%5,%6,%7}, {%8,%9}, {%0,%1,%2,%3};"
        : "+f"(c[0]), "+f"(c[1]), "+f"(c[2]), "+f"(c[3])
        : "r"(a[0]), "r"(a[1]), "r"(a[2]), "r"(a[3]), "r"(b[0]), "r"(b[1]));
}

__device__ __forceinline__ void ldm_x4(uint32_t* r, uint32_t addr) {
    asm volatile("ldmatrix.sync.aligned.m8n8.x4.shared.b16 {%0,%1,%2,%3}, [%4];"
        : "=r"(r[0]), "=r"(r[1]), "=r"(r[2]), "=r"(r[3]) : "r"(addr));
}

__device__ __forceinline__ void ldm_x4_t(uint32_t* r, uint32_t addr) {
    asm volatile("ldmatrix.sync.aligned.m8n8.x4.trans.shared.b16 {%0,%1,%2,%3}, [%4];"
        : "=r"(r[0]), "=r"(r[1]), "=r"(r[2]), "=r"(r[3]) : "r"(addr));
}

__device__ __forceinline__ uint32_t pack2(float lo, float hi) {
    __half2 h = __floats2half2_rn(lo, hi);
    return *(const uint32_t*)&h;
}

__global__ __launch_bounds__(THREADS, 1)
void gat_ldm_kernel(const float* __restrict__ x,
                    const float* __restrict__ Ww,
                    const float* __restrict__ Wb,
                    const float* __restrict__ aw,
                    const float* __restrict__ ab,
                    float* __restrict__ out)
{
    extern __shared__ char smc[];
    float* misc = (float*)(smc + MISCB);
    const uint32_t smb = smem_u32(smc);

    const int tid  = threadIdx.x;
    const int lane = tid & 31;
    const int warp = tid >> 5;
    const int wr   = warp >> 3;      // 0..1: 64-row block
    const int wc   = warp & 7;       // 0..7: 32-col block
    const int lq   = lane >> 2;      // 0..7
    const int lk   = lane & 3;       // 0..3
    const int b    = blockIdx.x;

    // ldmatrix lane address components
    const int lrow = lane & 7;             // row within 8x8
    const int ga   = (lane >> 3) & 1;      // group bit 0
    const int gb   = lane >> 4;            // group bit 1
    const uint32_t a_roff = (uint32_t)(lrow + ga * 8);   // A: +8 rows (matrices 1,3)
    const uint32_t a_koff = (uint32_t)(gb * 8);          // A: +8 k (matrices 2,3)
    const uint32_t b_roff = (uint32_t)(lrow + gb * 8);   // B: +8 n rows (matrices 2,3)
    const uint32_t b_koff = (uint32_t)(ga * 8);          // B: +8 k (matrices 1,3)

    const float* xb = x + (size_t)b * C_ * T_;

    // param preload
    if (tid < 256) {
        misc[M_WB + tid]   = Wb[tid];
        misc[M_ASRC + tid] = aw[tid];
        misc[M_ADST + tid] = aw[H_ + tid];
    }
    if (tid == 0) misc[M_AB] = ab[0];

    const int srow  = tid >> 3;      // 0..63
    const int sslot = tid & 7;       // 0..7 (k/4)

    float4 px[2], pw[4];

    auto ldg_chunk = [&](int c) {
        const float* xsrc = xb + c * KC;
        const float* wsrc = Ww + c * KC;
        #pragma unroll
        for (int i = 0; i < 2; i++)
            px[i] = *(const float4*)(xsrc + (srow + 64 * i) * T_ + sslot * 4);
        #pragma unroll
        for (int i = 0; i < 4; i++)
            pw[i] = *(const float4*)(wsrc + (srow + 64 * i) * T_ + sslot * 4);
    };

    auto sts_chunk = [&](int stage_byte) {
        __half* xs = (__half*)(smc + stage_byte);
        __half* ws = (__half*)(smc + stage_byte + WOFF2);
        #pragma unroll
        for (int i = 0; i < 2; i++) {
            uint2 u;
            u.x = pack2(px[i].x, px[i].y);
            u.y = pack2(px[i].z, px[i].w);
            *(uint2*)(xs + (srow + 64 * i) * XROW + sslot * 4) = u;
        }
        #pragma unroll
        for (int i = 0; i < 4; i++) {
            uint2 u;
            u.x = pack2(pw[i].x, pw[i].y);
            u.y = pack2(pw[i].z, pw[i].w);
            *(uint2*)(ws + (srow + 64 * i) * XROW + sslot * 4) = u;
        }
    };

    float acc[4][4][4];
    #pragma unroll
    for (int mb = 0; mb < 4; mb++)
        #pragma unroll
        for (int nb = 0; nb < 4; nb++)
            #pragma unroll
            for (int q = 0; q < 4; q++) acc[mb][nb][q] = 0.f;

    ldg_chunk(0);
    sts_chunk(ST0);
    ldg_chunk(1);

    // ---- Phase 1: h = x @ Ww^T ----
    for (int c = 0; c < CHUNKS; c++) {
        __syncthreads();
        if (c + 1 < CHUNKS) {
            sts_chunk((c + 1) & 1 ? ST1 : ST0);
            if (c + 2 < CHUNKS) ldg_chunk(c + 2);
        }
        const uint32_t xs_u = smb + ((c & 1) ? ST1 : ST0);
        const uint32_t ws_u = xs_u + WOFF2;

        #pragma unroll
        for (int kq = 0; kq < 2; kq++) {
            const uint32_t k0 = (uint32_t)(kq * 16);
            uint32_t afr[4][4];
            #pragma unroll
            for (int mb = 0; mb < 4; mb++)
                ldm_x4(afr[mb],
                    xs_u + (((uint32_t)(wr * 64 + mb * 16) + a_roff) * XROW + k0 + a_koff) * 2);
            uint32_t bfr[2][4];
            #pragma unroll
            for (int nbp = 0; nbp < 2; nbp++)
                ldm_x4(bfr[nbp],
                    ws_u + (((uint32_t)(wc * 32 + nbp * 16) + b_roff) * XROW + k0 + b_koff) * 2);
            #pragma unroll
            for (int mb = 0; mb < 4; mb++)
                #pragma unroll
                for (int nbp = 0; nbp < 2; nbp++) {
                    mma16(acc[mb][2 * nbp],     afr[mb], &bfr[nbp][0]);
                    mma16(acc[mb][2 * nbp + 1], afr[mb], &bfr[nbp][2]);
                }
        }
    }
    __syncthreads();

    // ---- Epilogue 1: bias add; f,g partials from f32 acc; h row-major fp16 ----
    {
        __half* ht = (__half*)(smc + HT);
        #pragma unroll
        for (int mb = 0; mb < 4; mb++) {
            #pragma unroll
            for (int half = 0; half < 2; half++) {
                int r = wr * 64 + mb * 16 + lq + half * 8;
                float f_ = 0.f, g_ = 0.f;
                #pragma unroll
                for (int nb = 0; nb < 4; nb++) {
                    int col = wc * 32 + nb * 8 + 2 * lk;
                    float h0 = acc[mb][nb][half * 2 + 0] + misc[M_WB + col];
                    float h1 = acc[mb][nb][half * 2 + 1] + misc[M_WB + col + 1];
                    f_ += h0 * misc[M_ASRC + col] + h1 * misc[M_ASRC + col + 1];
                    g_ += h0 * misc[M_ADST + col] + h1 * misc[M_ADST + col + 1];
                    *(uint32_t*)(ht + r * HTROW + col) = pack2(h0, h1);
                }
                f_ += __shfl_xor_sync(0xFFFFFFFF, f_, 1);
                f_ += __shfl_xor_sync(0xFFFFFFFF, f_, 2);
                g_ += __shfl_xor_sync(0xFFFFFFFF, g_, 1);
                g_ += __shfl_xor_sync(0xFFFFFFFF, g_, 2);
                if (lk == 0) {
                    misc[M_FP + wc * 128 + r] = f_;
                    misc[M_GP + wc * 128 + r] = g_;
                }
            }
        }
    }
    __syncthreads();
    if (tid < 128) {
        float s = 0.f;
        #pragma unroll
        for (int p = 0; p < 8; p++) s += misc[M_FP + p * 128 + tid];
        misc[M_FV + tid] = s;
    } else if (tid < 256) {
        int r = tid - 128;
        float s = 0.f;
        #pragma unroll
        for (int p = 0; p < 8; p++) s += misc[M_GP + p * 128 + r];
        misc[M_GV + r] = s;
    }
    __syncthreads();

    // ---- Phase 2: softmax over i; alpha -> fp16 row-major [i][k=j] ----
    {
        __half* ah = (__half*)(smc + AH);
        const int j = tid & 127, part = tid >> 7;   // 4 parts x 32 i's
        const float gj = misc[M_GV + j] + misc[M_AB];
        float s = 0.f;
        const int i0 = part * 32;
        #pragma unroll 4
        for (int i = i0; i < i0 + 32; i++) {
            float z = misc[M_FV + i] + gj;
            z = (z > 0.f) ? z : 0.2f * z;
            float ex = __expf(z);
            ah[i * AROW + j] = __float2half_rn(ex);
            s += ex;
        }
        misc[M_SP + part * 128 + j] = s;
        __syncthreads();
        if (tid < 128)
            misc[M_SINV + tid] = 1.0f /
                ((misc[M_SP + tid] + misc[M_SP + 128 + tid]) +
                 (misc[M_SP + 256 + tid] + misc[M_SP + 384 + tid]));
        __syncthreads();
        const float iv = misc[M_SINV + j];
        #pragma unroll 4
        for (int i = i0; i < i0 + 32; i++) {
            __half* p = ah + i * AROW + j;
            *p = __float2half_rn(__half2float(*p) * iv);
        }
    }
    __syncthreads();

    // ---- Phase 3: out = alpha @ h (A: ldmatrix, B: ldmatrix.trans) ----
    #pragma unroll
    for (int mb = 0; mb < 4; mb++)
        #pragma unroll
        for (int nb = 0; nb < 4; nb++)
            #pragma unroll
            for (int q = 0; q < 4; q++) acc[mb][nb][q] = 0.f;

    {
        const uint32_t ah_u = smb + AH;
        const uint32_t ht_u = smb + HT;
        #pragma unroll 2
        for (int kq = 0; kq < 8; kq++) {
            const uint32_t k0 = (uint32_t)(kq * 16);
            uint32_t afr[4][4];
            #pragma unroll
            for (int mb = 0; mb < 4; mb++)
                ldm_x4(afr[mb],
                    ah_u + (((uint32_t)(wr * 64 + mb * 16) + a_roff) * AROW + k0 + a_koff) * 2);
            // trans B: matrices 0..3 = (k0-7,n0-7),(k8-15,n0-7),(k0-7,n8-15),(k8-15,n8-15)
            uint32_t bfr[2][4];
            #pragma unroll
            for (int nbp = 0; nbp < 2; nbp++)
                ldm_x4_t(bfr[nbp],
                    ht_u + ((k0 + a_roff) * HTROW + (uint32_t)(wc * 32 + nbp * 16 + gb * 8)) * 2);
            #pragma unroll
            for (int mb = 0; mb < 4; mb++)
                #pragma unroll
                for (int nbp = 0; nbp < 2; nbp++) {
                    mma16(acc[mb][2 * nbp],     afr[mb], &bfr[nbp][0]);
                    mma16(acc[mb][2 * nbp + 1], afr[mb], &bfr[nbp][2]);
                }
        }
    }

    // ---- Epilogue 2: store out ----
    {
        float* ob = out + (size_t)b * C_ * H_;
        #pragma unroll
        for (int mb = 0; mb < 4; mb++) {
            int r  = wr * 64 + mb * 16 + lq;
            int r2 = r + 8;
            #pragma unroll
            for (int nb = 0; nb < 4; nb++) {
                int j0 = wc * 32 + nb * 8 + 2 * lk;
                *(float2*)&ob[r  * H_ + j0] = make_float2(acc[mb][nb][0], acc[mb][nb][1]);
                *(float2*)&ob[r2 * H_ + j0] = make_float2(acc[mb][nb][2], acc[mb][nb][3]);
            }
        }
    }
}

extern "C" void kernel_launch(void* const* d_in, const int* in_sizes, int n_in,
                              void* d_out, int out_size)
{
    const float* x  = (const float*)d_in[0];
    const float* Ww = (const float*)d_in[1];
    const float* Wb = (const float*)d_in[2];
    const float* aw = (const float*)d_in[3];
    const float* ab = (const float*)d_in[4];
    float* out = (float*)d_out;

    cudaFuncSetAttribute(gat_ldm_kernel,
                         cudaFuncAttributeMaxDynamicSharedMemorySize, SMEM_BYTES);

    gat_ldm_kernel<<<B_, THREADS, SMEM_BYTES>>>(x, Ww, Wb, aw, ab, out);
}